// round 10
// baseline (speedup 1.0000x reference)
#include <cuda_runtime.h>
#include <math.h>

// ---------------- problem constants ----------------
#define NI      16          // instances; iid = class*8 + b
#define HW      409600      // 640*640
#define HW4     102400      // HW/4
#define NCH     12
#define NMAPS   6
#define EPSF    1e-4
#define DB      37          // dice blocks per instance (16*37 = 592 = 148 SMs * 4 CTAs: ONE wave)
#define RBPI    18          // rare-kernel blocks per instance
#define RNB     (NI*RBPI)   // 288 (co-resident: 148 SMs * 2)
#define NACC    23          // 0..2 textA  3..5 textB  6..10 a_k  11..15 b_k  16..20 c_k  21 pos  22 neg

// ---------------- device scratch ----------------
__device__ unsigned g_ddone;                  // completion counter for k_dice
__device__ unsigned g_bar;                    // grid barrier counter for k_rare
__device__ int      g_mode[NI];               // 0=select-all(A) 1=fallback(B) 2=hist
__device__ int      g_anyhist;
__device__ unsigned long long g_k[NI];
__device__ float    g_thr[NI];
__device__ unsigned g_selhi[NI], g_krem[NI];
__device__ unsigned g_histhi[NI][8192];       // rare path only (stays zero on fast path)
__device__ unsigned g_histlo[NI][524288];     // rare path only
__device__ double   g_sums[NI][NACC];
__device__ double   g_fix[NI][3];             // exact text sums (rare path)

// ---------------- helpers ----------------
__device__ __forceinline__ float fsigmoid(float x) {
    float t;
    asm("tanh.approx.f32 %0, %1;" : "=f"(t) : "f"(0.5f * x));
    return fmaf(0.5f, t, 0.5f);
}
__device__ __forceinline__ unsigned keyOf(float x) {
    unsigned u = __float_as_uint(x);
    return (u & 0x80000000u) ? ~u : (u | 0x80000000u);
}
__device__ __forceinline__ float unkey(unsigned k) {
    unsigned u = (k & 0x80000000u) ? (k ^ 0x80000000u) : ~k;
    return __uint_as_float(u);
}

// ---------------- finalize: pick per-mode text sums, write 3 outputs ----------------
__device__ void finalize_write(float* out) {
    double ltc[2] = {0.0, 0.0}, lkc[2] = {0.0, 0.0};
    for (int t = 0; t < NI; t++) {
        int cls = t >> 3;
        int mode = *(volatile int*)&g_mode[t];
        double a, bb, cc;
        if (mode == 2)      { a = *(volatile double*)&g_fix[t][0];
                              bb = *(volatile double*)&g_fix[t][1];
                              cc = *(volatile double*)&g_fix[t][2]; }
        else if (mode == 1) { a = *(volatile double*)&g_sums[t][3];
                              bb = *(volatile double*)&g_sums[t][4];
                              cc = *(volatile double*)&g_sums[t][5]; }
        else                { a = *(volatile double*)&g_sums[t][0];
                              bb = *(volatile double*)&g_sums[t][1];
                              cc = *(volatile double*)&g_sums[t][2]; }
        double lt = 1.0 - 2.0 * a / ((bb + EPSF) + (cc + EPSF));
        double lk = 0.0;
        for (int j = 0; j < 5; j++) {
            double aj = *(volatile double*)&g_sums[t][6 + j];
            double bj = *(volatile double*)&g_sums[t][11 + j] + EPSF;
            double cj = *(volatile double*)&g_sums[t][16 + j] + EPSF;
            lk += 1.0 - 2.0 * aj / (bj + cj);
        }
        lk *= 0.2;
        ltc[cls] += lt; lkc[cls] += lk;
    }
    double lt0 = ltc[0] * 0.125, lt1 = ltc[1] * 0.125;
    double lk0 = lkc[0] * 0.125, lk1 = lkc[1] * 0.125;
    double l0 = 0.7 * lt0 + 0.3 * lk0;
    double l1 = 0.7 * lt1 + 0.3 * lk1;
    out[0] = (float)(0.5 * (l0 + l1));
    out[1] = (float)(0.5 * (lt0 + lt1));
    out[2] = (float)(0.5 * (lk0 + lk1));
}

// ---------------- kernel 1: clear scratch ----------------
__global__ void k_clear() {
    int t = threadIdx.x;
    if (t == 0) { g_ddone = 0u; g_bar = 0u; g_anyhist = 0; }
    double* s = &g_sums[0][0];
    for (int i = t; i < NI * NACC; i += blockDim.x) s[i] = 0.0;
    double* f = &g_fix[0][0];
    for (int i = t; i < NI * 3; i += blockDim.x) f[i] = 0.0;
}

// ---------------- kernel 2: fused everything (dual-variant dice + counts) ----------------
__global__ void __launch_bounds__(256, 4) k_dice(const float* __restrict__ outs,
                                                 const float* __restrict__ labs,
                                                 const float* __restrict__ tmg,
                                                 float* __restrict__ out) {
    int inst = blockIdx.x / DB;
    int cb   = blockIdx.x % DB;
    int b = inst >> 1, i = inst & 1;   // interleaved -> tm L2 reuse across class pair
    int iid = i * 8 + b;

    const float4* ob = (const float4*)outs + ((size_t)b * NCH + i * NMAPS) * HW4;
    const float4* lb = (const float4*)labs + ((size_t)b * NCH + i * NMAPS) * HW4;
    const float4* m4 = (const float4*)tmg  + (size_t)b * HW4;

    float acc[NACC];
    #pragma unroll
    for (int j = 0; j < NACC; j++) acc[j] = 0.f;

    for (int idx = cb * 256 + threadIdx.x; idx < HW4; idx += DB * 256) {
        float4 t = ob[5 * HW4 + idx];
        float4 g = lb[5 * HW4 + idx];
        float4 m = m4[idx];
        float tv[4] = {t.x, t.y, t.z, t.w};
        float gv[4] = {g.x, g.y, g.z, g.w};
        float mv[4] = {m.x, m.y, m.z, m.w};
        float selk[4];
        #pragma unroll
        for (int e = 0; e < 4; e++) {
            float sc = tv[e], gval = gv[e], mval = mv[e];
            bool tmb = mval > 0.5f;
            bool gtb = gval > 0.5f;
            float wA = tmb ? 1.f : 0.f;
            float wB = mval * mval;          // fallback: sel = tm  -> weights tm, tm^2 handled below
            float sg = fsigmoid(sc);
            float b0 = sg * gval, b1 = sg * sg, b2 = gval * gval;
            acc[0] = fmaf(wA, b0, acc[0]);
            acc[1] = fmaf(wA, b1, acc[1]);
            acc[2] = fmaf(wA, b2, acc[2]);
            acc[3] = fmaf(wB, b0, acc[3]);
            acc[4] = fmaf(wB, b1, acc[4]);
            acc[5] = fmaf(wB, b2, acc[5]);
            acc[21] += (gtb && tmb) ? 1.f : 0.f;   // pos
            acc[22] += gtb ? 0.f : 1.f;            // neg
            selk[e] = (sc > 0.f && tmb) ? 1.f : 0.f;
        }
        #pragma unroll
        for (int j = 0; j < 5; j++) {
            float4 kv = ob[(size_t)j * HW4 + idx];
            float4 gk = lb[(size_t)j * HW4 + idx];
            float kvv[4] = {kv.x, kv.y, kv.z, kv.w};
            float gkk[4] = {gk.x, gk.y, gk.z, gk.w};
            #pragma unroll
            for (int e = 0; e < 4; e++) {
                float sg = fsigmoid(kvv[e]);
                float p = sg * selk[e], tt = gkk[e] * selk[e];
                acc[6 + j]  = fmaf(p, tt, acc[6 + j]);
                acc[11 + j] = fmaf(p, p,  acc[11 + j]);
                acc[16 + j] = fmaf(tt, tt, acc[16 + j]);
            }
        }
    }

    #pragma unroll
    for (int j = 0; j < NACC; j++) {
        float v = acc[j];
        #pragma unroll
        for (int o = 16; o; o >>= 1) v += __shfl_down_sync(0xffffffffu, v, o);
        acc[j] = v;
    }
    __shared__ float bsum[NACC];
    if (threadIdx.x < NACC) bsum[threadIdx.x] = 0.f;
    __syncthreads();
    if ((threadIdx.x & 31) == 0) {
        #pragma unroll
        for (int j = 0; j < NACC; j++) atomicAdd(&bsum[j], acc[j]);
    }
    __syncthreads();
    if (threadIdx.x < NACC) atomicAdd(&g_sums[iid][threadIdx.x], (double)bsum[threadIdx.x]);

    // ---- last-finishing block: decide modes; finalize if no hist path needed ----
    __shared__ unsigned amLast;
    __threadfence();
    if (threadIdx.x == 0)
        amLast = (atomicAdd(&g_ddone, 1u) == (unsigned)gridDim.x - 1u) ? 1u : 0u;
    __syncthreads();
    if (amLast) {
        __shared__ int any;
        if (threadIdx.x == 0) any = 0;
        __syncthreads();
        if (threadIdx.x < NI) {
            int t = threadIdx.x;
            unsigned long long p = (unsigned long long)(*(volatile double*)&g_sums[t][21] + 0.5);
            unsigned long long n = (unsigned long long)(*(volatile double*)&g_sums[t][22] + 0.5);
            unsigned long long k = p * 3ull;
            if (k > n) k = n;
            int mode;
            if (p == 0ull || k == 0ull) mode = 1;
            else if (k == n)            mode = 0;
            else                        { mode = 2; atomicExch(&any, 1); }
            g_mode[t] = mode; g_k[t] = k;
        }
        __syncthreads();
        if (threadIdx.x == 0) {
            g_anyhist = any;
            __threadfence();
            if (!any) finalize_write(out);
        }
    }
}

// ---------------- kernel 3 (persistent, guarded): exact OHEM path ----------------
__device__ __forceinline__ void gridbar(int phase) {
    __syncthreads();
    __threadfence();
    if (threadIdx.x == 0) {
        atomicAdd(&g_bar, 1u);
        unsigned tgt = (unsigned)phase * (unsigned)RNB;
        while (*(volatile unsigned*)&g_bar < tgt) { }
    }
    __syncthreads();
    __threadfence();
}

__global__ void __launch_bounds__(256, 2) k_rare(const float* __restrict__ outs,
                                                 const float* __restrict__ labs,
                                                 const float* __restrict__ tmg,
                                                 float* __restrict__ out) {
    if (*(volatile int*)&g_anyhist == 0) return;     // fast path: all 288 blocks exit

    const int blk = blockIdx.x;
    const int inst_lin = blk / RBPI;
    const int slice = blk % RBPI;
    const int b = inst_lin >> 1, i = inst_lin & 1;
    const int iid = i * 8 + b;
    const int tid = threadIdx.x;
    const int mymode = *(volatile int*)&g_mode[iid];

    const int ch = i * NMAPS + (NMAPS - 1);
    const float4* sc4 = (const float4*)outs + ((size_t)b * NCH + ch) * HW4;
    const float4* gt4 = (const float4*)labs + ((size_t)b * NCH + ch) * HW4;
    const float4* m4  = (const float4*)tmg + (size_t)b * HW4;

    __shared__ unsigned shist[8192];
    __shared__ unsigned long long csum[256];

    // phase 1: top-13-bit histogram of negative keys
    if (mymode == 2) {
        for (int j = tid; j < 8192; j += 256) shist[j] = 0u;
        __syncthreads();
        for (int idx = slice * 256 + tid; idx < HW4; idx += RBPI * 256) {
            float4 s = sc4[idx]; float4 g = gt4[idx];
            float sv[4] = {s.x, s.y, s.z, s.w};
            float gg[4] = {g.x, g.y, g.z, g.w};
            #pragma unroll
            for (int e = 0; e < 4; e++)
                if (gg[e] <= 0.5f) atomicAdd(&shist[keyOf(sv[e]) >> 19], 1u);
        }
        __syncthreads();
        for (int j = tid; j < 8192; j += 256) {
            unsigned c = shist[j];
            if (c) atomicAdd(&g_histhi[iid][j], c);
        }
    }
    gridbar(1);

    // phase 2: scan hi descending (block t handles instance t)
    if (blk < NI && *(volatile int*)&g_mode[blk] == 2) {
        unsigned long long s = 0;
        int hi = 8192 - tid * 32;
        for (int bn = hi - 1; bn >= hi - 32; bn--) s += g_histhi[blk][bn];
        csum[tid] = s;
        __syncthreads();
        if (tid == 0) {
            unsigned long long k = g_k[blk], cum = 0;
            for (int c = 0; c < 256; c++) {
                if (cum + csum[c] >= k) {
                    int h2 = 8192 - c * 32;
                    for (int bn = h2 - 1; bn >= h2 - 32; bn--) {
                        unsigned long long hv = g_histhi[blk][bn];
                        if (cum + hv >= k) { g_selhi[blk] = (unsigned)bn; g_krem[blk] = (unsigned)(k - cum); goto donehi; }
                        cum += hv;
                    }
                }
                cum += csum[c];
            }
            donehi: ;
        }
    }
    gridbar(2);

    // phase 3: low-19-bit histogram among matching hi-bin
    if (mymode == 2) {
        unsigned sel = *(volatile unsigned*)&g_selhi[iid];
        for (int idx = slice * 256 + tid; idx < HW4; idx += RBPI * 256) {
            float4 s = sc4[idx]; float4 g = gt4[idx];
            float sv[4] = {s.x, s.y, s.z, s.w};
            float gg[4] = {g.x, g.y, g.z, g.w};
            #pragma unroll
            for (int e = 0; e < 4; e++) {
                if (gg[e] <= 0.5f) {
                    unsigned kk = keyOf(sv[e]);
                    if ((kk >> 19) == sel) atomicAdd(&g_histlo[iid][kk & 0x7FFFFu], 1u);
                }
            }
        }
    }
    gridbar(3);

    // phase 4: scan lo -> exact threshold
    if (blk < NI && *(volatile int*)&g_mode[blk] == 2) {
        unsigned long long s = 0;
        int hi = 524288 - tid * 2048;
        for (int bn = hi - 1; bn >= hi - 2048; bn--) s += g_histlo[blk][bn];
        csum[tid] = s;
        __syncthreads();
        if (tid == 0) {
            unsigned long long k = (unsigned long long)g_krem[blk], cum = 0;
            unsigned sel = g_selhi[blk];
            for (int c = 0; c < 256; c++) {
                if (cum + csum[c] >= k) {
                    int h2 = 524288 - c * 2048;
                    for (int bn = h2 - 1; bn >= h2 - 2048; bn--) {
                        unsigned long long hv = g_histlo[blk][bn];
                        if (cum + hv >= k) { g_thr[blk] = unkey((sel << 19) | (unsigned)bn); goto donelo; }
                        cum += hv;
                    }
                }
                cum += csum[c];
            }
            donelo: ;
        }
    }
    gridbar(4);

    // phase 5: exact text dice sums with real threshold; clear dirtied hists
    if (mymode == 2) {
        float thr = *(volatile float*)&g_thr[iid];
        float a0 = 0.f, a1 = 0.f, a2 = 0.f;
        for (int idx = slice * 256 + tid; idx < HW4; idx += RBPI * 256) {
            float4 s = sc4[idx]; float4 g = gt4[idx]; float4 m = m4[idx];
            float sv[4] = {s.x, s.y, s.z, s.w};
            float gg[4] = {g.x, g.y, g.z, g.w};
            float mm[4] = {m.x, m.y, m.z, m.w};
            #pragma unroll
            for (int e = 0; e < 4; e++) {
                float st = (((sv[e] >= thr) || (gg[e] > 0.5f)) && (mm[e] > 0.5f)) ? 1.f : 0.f;
                float sg = fsigmoid(sv[e]);
                a0 = fmaf(st, sg * gg[e], a0);
                a1 = fmaf(st, sg * sg, a1);
                a2 = fmaf(st, gg[e] * gg[e], a2);
            }
        }
        #pragma unroll
        for (int o = 16; o; o >>= 1) {
            a0 += __shfl_down_sync(0xffffffffu, a0, o);
            a1 += __shfl_down_sync(0xffffffffu, a1, o);
            a2 += __shfl_down_sync(0xffffffffu, a2, o);
        }
        __shared__ float fx[3];
        if (tid < 3) fx[tid] = 0.f;
        __syncthreads();
        if ((tid & 31) == 0) {
            atomicAdd(&fx[0], a0); atomicAdd(&fx[1], a1); atomicAdd(&fx[2], a2);
        }
        __syncthreads();
        if (tid < 3) atomicAdd(&g_fix[iid][tid], (double)fx[tid]);
    }
    {   // clear histograms so next graph replay starts zeroed
        unsigned* hi2 = &g_histhi[0][0];
        unsigned* lo2 = &g_histlo[0][0];
        int gt0 = blk * 256 + tid, gs = RNB * 256;
        for (int j = gt0; j < NI * 8192; j += gs) hi2[j] = 0u;
        for (size_t j = gt0; j < (size_t)NI * 524288; j += gs) lo2[j] = 0u;
    }
    gridbar(5);

    if (blk == 0 && tid == 0) finalize_write(out);
}

// ---------------- launch ----------------
extern "C" void kernel_launch(void* const* d_in, const int* in_sizes, int n_in,
                              void* d_out, int out_size) {
    const float* outs = (const float*)d_in[0];
    const float* labs = (const float*)d_in[1];
    const float* tmg  = (const float*)d_in[2];
    float* out = (float*)d_out;

    k_clear<<<1, 256>>>();
    k_dice<<<NI * DB, 256>>>(outs, labs, tmg, out);
    k_rare<<<RNB, 256>>>(outs, labs, tmg, out);    // idle (~1 launch) on fast path
}

// round 11
// speedup vs baseline: 1.6023x; 1.6023x over previous
#include <cuda_runtime.h>
#include <math.h>

// ---------------- problem constants ----------------
#define NI      16          // instances; iid = class*8 + b
#define HW      409600      // 640*640
#define HW4     102400      // HW/4
#define NCH     12
#define NMAPS   6
#define EPSF    1e-4
#define CB      74          // count blocks per batch image (8*74 = 592)
#define DB      37          // dice blocks per instance (16*37 = 592 = 148 SMs * 4 CTAs: ONE wave)
#define RBPI    18          // rare-kernel blocks per instance
#define RNB     (NI*RBPI)   // 288 (co-resident: 148 SMs * 2)

// ---------------- device scratch (zero-initialized at load; self-cleaned each run) ----------------
__device__ unsigned g_cdone;                  // completion counter for k_count
__device__ unsigned g_ddone;                  // completion counter for k_dice
__device__ unsigned g_bar;                    // grid barrier counter for k_rare
__device__ unsigned g_pos[NI], g_neg[NI];
__device__ int      g_mode[NI];               // 0=select-all 1=fallback 2=hist
__device__ int      g_fallback[NI];
__device__ int      g_anyhist;
__device__ unsigned long long g_k[NI];
__device__ float    g_thr[NI];
__device__ unsigned g_selhi[NI], g_krem[NI];
__device__ unsigned g_histhi[NI][8192];       // rare path only (stays zero on fast path)
__device__ unsigned g_histlo[NI][524288];     // rare path only
__device__ double   g_sums[NI][18];           // [0..2]=text a,b,c ; [3+j]=a_k ; [8+j]=b_k ; [13+j]=c_k

// ---------------- helpers ----------------
__device__ __forceinline__ float fsigmoid(float x) {
    float t;
    asm("tanh.approx.f32 %0, %1;" : "=f"(t) : "f"(0.5f * x));
    return fmaf(0.5f, t, 0.5f);
}
__device__ __forceinline__ unsigned keyOf(float x) {
    unsigned u = __float_as_uint(x);
    return (u & 0x80000000u) ? ~u : (u | 0x80000000u);
}
__device__ __forceinline__ float unkey(unsigned k) {
    unsigned u = (k & 0x80000000u) ? (k ^ 0x80000000u) : ~k;
    return __uint_as_float(u);
}

// ---------------- kernel 1: pos/neg counts + decide in last block ----------------
__global__ void __launch_bounds__(256) k_count(const float* __restrict__ labs,
                                               const float* __restrict__ tmg) {
    int b  = blockIdx.x / CB;
    int cb = blockIdx.x % CB;
    const float4* g0 = (const float4*)labs + ((size_t)b * NCH + 5)  * HW4;
    const float4* g1 = (const float4*)labs + ((size_t)b * NCH + 11) * HW4;
    const float4* m4 = (const float4*)tmg  + (size_t)b * HW4;

    unsigned p0 = 0, n0 = 0, p1 = 0, n1 = 0;
    for (int idx = cb * 256 + threadIdx.x; idx < HW4; idx += CB * 256) {
        float4 a = g0[idx]; float4 c = g1[idx]; float4 m = m4[idx];
        float av[4] = {a.x, a.y, a.z, a.w};
        float cv[4] = {c.x, c.y, c.z, c.w};
        float mv[4] = {m.x, m.y, m.z, m.w};
        #pragma unroll
        for (int e = 0; e < 4; e++) {
            bool tm = mv[e] > 0.5f;
            if (av[e] > 0.5f) { if (tm) p0++; } else n0++;
            if (cv[e] > 0.5f) { if (tm) p1++; } else n1++;
        }
    }
    #pragma unroll
    for (int o = 16; o; o >>= 1) {
        p0 += __shfl_down_sync(0xffffffffu, p0, o);
        n0 += __shfl_down_sync(0xffffffffu, n0, o);
        p1 += __shfl_down_sync(0xffffffffu, p1, o);
        n1 += __shfl_down_sync(0xffffffffu, n1, o);
    }
    __shared__ unsigned sp0, sn0, sp1, sn1;
    if (threadIdx.x == 0) { sp0 = sn0 = sp1 = sn1 = 0u; }
    __syncthreads();
    if ((threadIdx.x & 31) == 0) {
        atomicAdd(&sp0, p0); atomicAdd(&sn0, n0);
        atomicAdd(&sp1, p1); atomicAdd(&sn1, n1);
    }
    __syncthreads();
    if (threadIdx.x == 0) {
        atomicAdd(&g_pos[b],     sp0); atomicAdd(&g_neg[b],     sn0);
        atomicAdd(&g_pos[8 + b], sp1); atomicAdd(&g_neg[8 + b], sn1);
    }

    // last-finishing block runs decide
    __shared__ unsigned amLast;
    __threadfence();
    if (threadIdx.x == 0)
        amLast = (atomicAdd(&g_cdone, 1u) == (unsigned)gridDim.x - 1u) ? 1u : 0u;
    __syncthreads();
    if (amLast) {
        __shared__ int any;
        if (threadIdx.x == 0) any = 0;
        __syncthreads();
        if (threadIdx.x < NI) {
            int t = threadIdx.x;
            unsigned p = *(volatile unsigned*)&g_pos[t];
            unsigned n = *(volatile unsigned*)&g_neg[t];
            unsigned long long k = (unsigned long long)p * 3ull;
            if (k > n) k = n;
            int mode, fb = 0; float thr = 0.f;
            if (p == 0u || k == 0ull)           { mode = 1; fb = 1; }
            else if (k == (unsigned long long)n){ mode = 0; thr = -INFINITY; }
            else                                 { mode = 2; atomicExch(&any, 1); }
            g_mode[t] = mode; g_fallback[t] = fb; g_thr[t] = thr; g_k[t] = k;
        }
        __syncthreads();
        if (threadIdx.x == 0) { g_anyhist = any; __threadfence(); }
    }
}

// ---------------- kernel 2 (persistent, guarded): exact radix-select threshold ----------------
__device__ __forceinline__ void gridbar(int phase) {
    __syncthreads();
    __threadfence();
    if (threadIdx.x == 0) {
        atomicAdd(&g_bar, 1u);
        unsigned tgt = (unsigned)phase * (unsigned)RNB;
        while (*(volatile unsigned*)&g_bar < tgt) { }
    }
    __syncthreads();
    __threadfence();
}

__global__ void __launch_bounds__(256, 2) k_rare(const float* __restrict__ outs,
                                                 const float* __restrict__ labs) {
    if (*(volatile int*)&g_anyhist == 0) return;     // fast path: all 288 blocks exit

    const int blk = blockIdx.x;
    const int inst_lin = blk / RBPI;
    const int slice = blk % RBPI;
    const int b = inst_lin >> 1, i = inst_lin & 1;
    const int iid = i * 8 + b;
    const int tid = threadIdx.x;
    const int mymode = *(volatile int*)&g_mode[iid];

    const int ch = i * NMAPS + (NMAPS - 1);
    const float4* sc4 = (const float4*)outs + ((size_t)b * NCH + ch) * HW4;
    const float4* gt4 = (const float4*)labs + ((size_t)b * NCH + ch) * HW4;

    __shared__ unsigned shist[8192];
    __shared__ unsigned long long csum[256];

    // phase 1: top-13-bit histogram of negative keys
    if (mymode == 2) {
        for (int j = tid; j < 8192; j += 256) shist[j] = 0u;
        __syncthreads();
        for (int idx = slice * 256 + tid; idx < HW4; idx += RBPI * 256) {
            float4 s = sc4[idx]; float4 g = gt4[idx];
            float sv[4] = {s.x, s.y, s.z, s.w};
            float gg[4] = {g.x, g.y, g.z, g.w};
            #pragma unroll
            for (int e = 0; e < 4; e++)
                if (gg[e] <= 0.5f) atomicAdd(&shist[keyOf(sv[e]) >> 19], 1u);
        }
        __syncthreads();
        for (int j = tid; j < 8192; j += 256) {
            unsigned c = shist[j];
            if (c) atomicAdd(&g_histhi[iid][j], c);
        }
    }
    gridbar(1);

    // phase 2: scan hi descending (block t handles instance t)
    if (blk < NI && *(volatile int*)&g_mode[blk] == 2) {
        unsigned long long s = 0;
        int hi = 8192 - tid * 32;
        for (int bn = hi - 1; bn >= hi - 32; bn--) s += g_histhi[blk][bn];
        csum[tid] = s;
        __syncthreads();
        if (tid == 0) {
            unsigned long long k = g_k[blk], cum = 0;
            for (int c = 0; c < 256; c++) {
                if (cum + csum[c] >= k) {
                    int h2 = 8192 - c * 32;
                    for (int bn = h2 - 1; bn >= h2 - 32; bn--) {
                        unsigned long long hv = g_histhi[blk][bn];
                        if (cum + hv >= k) { g_selhi[blk] = (unsigned)bn; g_krem[blk] = (unsigned)(k - cum); goto donehi; }
                        cum += hv;
                    }
                }
                cum += csum[c];
            }
            donehi: ;
        }
    }
    gridbar(2);

    // phase 3: low-19-bit histogram among matching hi-bin
    if (mymode == 2) {
        unsigned sel = *(volatile unsigned*)&g_selhi[iid];
        for (int idx = slice * 256 + tid; idx < HW4; idx += RBPI * 256) {
            float4 s = sc4[idx]; float4 g = gt4[idx];
            float sv[4] = {s.x, s.y, s.z, s.w};
            float gg[4] = {g.x, g.y, g.z, g.w};
            #pragma unroll
            for (int e = 0; e < 4; e++) {
                if (gg[e] <= 0.5f) {
                    unsigned kk = keyOf(sv[e]);
                    if ((kk >> 19) == sel) atomicAdd(&g_histlo[iid][kk & 0x7FFFFu], 1u);
                }
            }
        }
    }
    gridbar(3);

    // phase 4: scan lo -> exact threshold; then clear dirtied histograms
    if (blk < NI && *(volatile int*)&g_mode[blk] == 2) {
        unsigned long long s = 0;
        int hi = 524288 - tid * 2048;
        for (int bn = hi - 1; bn >= hi - 2048; bn--) s += g_histlo[blk][bn];
        csum[tid] = s;
        __syncthreads();
        if (tid == 0) {
            unsigned long long k = (unsigned long long)g_krem[blk], cum = 0;
            unsigned sel = g_selhi[blk];
            for (int c = 0; c < 256; c++) {
                if (cum + csum[c] >= k) {
                    int h2 = 524288 - c * 2048;
                    for (int bn = h2 - 1; bn >= h2 - 2048; bn--) {
                        unsigned long long hv = g_histlo[blk][bn];
                        if (cum + hv >= k) { g_thr[blk] = unkey((sel << 19) | (unsigned)bn); goto donelo; }
                        cum += hv;
                    }
                }
                cum += csum[c];
            }
            donelo: ;
        }
    }
    __syncthreads();
    {   // clear histograms (+ barrier counter) so next run starts zeroed
        unsigned* hi2 = &g_histhi[0][0];
        unsigned* lo2 = &g_histlo[0][0];
        int gt0 = blk * 256 + tid, gs = RNB * 256;
        for (int j = gt0; j < NI * 8192; j += gs) hi2[j] = 0u;
        for (size_t j = gt0; j < (size_t)NI * 524288; j += gs) lo2[j] = 0u;
    }
    gridbar(4);
    if (blk == 0 && tid == 0) g_bar = 0u;   // reset barrier counter for next run
}

// ---------------- kernel 3: fused dice + finalize + scratch cleanup ----------------
__global__ void __launch_bounds__(256) k_dice(const float* __restrict__ outs,
                                              const float* __restrict__ labs,
                                              const float* __restrict__ tmg,
                                              float* __restrict__ out) {
    int inst = blockIdx.x / DB;
    int cb   = blockIdx.x % DB;
    int b = inst >> 1, i = inst & 1;
    int iid = i * 8 + b;
    const float thr = g_thr[iid];
    const int   fb  = g_fallback[iid];

    const float4* ob = (const float4*)outs + ((size_t)b * NCH + i * NMAPS) * HW4;
    const float4* lb = (const float4*)labs + ((size_t)b * NCH + i * NMAPS) * HW4;
    const float4* m4 = (const float4*)tmg  + (size_t)b * HW4;

    float acc[18];
    #pragma unroll
    for (int j = 0; j < 18; j++) acc[j] = 0.f;

    for (int idx = cb * 256 + threadIdx.x; idx < HW4; idx += DB * 256) {
        float4 t = ob[5 * HW4 + idx];
        float4 g = lb[5 * HW4 + idx];
        float4 m = m4[idx];
        float tv[4] = {t.x, t.y, t.z, t.w};
        float gv[4] = {g.x, g.y, g.z, g.w};
        float mv[4] = {m.x, m.y, m.z, m.w};
        float selk[4];
        #pragma unroll
        for (int e = 0; e < 4; e++) {
            float sc = tv[e], gval = gv[e], mval = mv[e];
            float st = fb ? mval
                          : (((sc >= thr) || (gval > 0.5f)) && (mval > 0.5f) ? 1.f : 0.f);
            float sg = fsigmoid(sc);
            float p = sg * st, tt = gval * st;
            acc[0] = fmaf(p, tt, acc[0]);
            acc[1] = fmaf(p, p,  acc[1]);
            acc[2] = fmaf(tt, tt, acc[2]);
            selk[e] = (sc > 0.f && mval > 0.5f) ? 1.f : 0.f;
        }
        #pragma unroll
        for (int j = 0; j < 5; j++) {
            float4 kv = ob[(size_t)j * HW4 + idx];
            float4 gk = lb[(size_t)j * HW4 + idx];
            float kvv[4] = {kv.x, kv.y, kv.z, kv.w};
            float gkk[4] = {gk.x, gk.y, gk.z, gk.w};
            #pragma unroll
            for (int e = 0; e < 4; e++) {
                float sg = fsigmoid(kvv[e]);
                float p = sg * selk[e], tt = gkk[e] * selk[e];
                acc[3 + j]  = fmaf(p, tt, acc[3 + j]);
                acc[8 + j]  = fmaf(p, p,  acc[8 + j]);
                acc[13 + j] = fmaf(tt, tt, acc[13 + j]);
            }
        }
    }

    #pragma unroll
    for (int j = 0; j < 18; j++) {
        float v = acc[j];
        #pragma unroll
        for (int o = 16; o; o >>= 1) v += __shfl_down_sync(0xffffffffu, v, o);
        acc[j] = v;
    }
    __shared__ float bsum[18];
    if (threadIdx.x < 18) bsum[threadIdx.x] = 0.f;
    __syncthreads();
    if ((threadIdx.x & 31) == 0) {
        #pragma unroll
        for (int j = 0; j < 18; j++) atomicAdd(&bsum[j], acc[j]);
    }
    __syncthreads();
    if (threadIdx.x < 18) atomicAdd(&g_sums[iid][threadIdx.x], (double)bsum[threadIdx.x]);

    // ---- last-finishing block: finalize 3 outputs, then self-clean ALL scratch ----
    __shared__ unsigned amLast;
    __threadfence();
    if (threadIdx.x == 0)
        amLast = (atomicAdd(&g_ddone, 1u) == (unsigned)gridDim.x - 1u) ? 1u : 0u;
    __syncthreads();
    if (amLast) {
        __shared__ double slt[NI], slk[NI];
        int t = threadIdx.x;
        if (t < NI) {
            double a  = *(volatile double*)&g_sums[t][0];
            double bb = *(volatile double*)&g_sums[t][1] + EPSF;
            double cc = *(volatile double*)&g_sums[t][2] + EPSF;
            double lt = 1.0 - 2.0 * a / (bb + cc);
            double lk = 0.0;
            for (int j = 0; j < 5; j++) {
                double aj = *(volatile double*)&g_sums[t][3 + j];
                double bj = *(volatile double*)&g_sums[t][8 + j] + EPSF;
                double cj = *(volatile double*)&g_sums[t][13 + j] + EPSF;
                lk += 1.0 - 2.0 * aj / (bj + cj);
            }
            lk *= 0.2;
            slt[t] = lt; slk[t] = lk;
        }
        __syncthreads();
        if (t == 0) {
            double lt0 = 0, lt1 = 0, lk0 = 0, lk1 = 0;
            for (int b2 = 0; b2 < 8; b2++) {
                lt0 += slt[b2];     lk0 += slk[b2];
                lt1 += slt[8 + b2]; lk1 += slk[8 + b2];
            }
            lt0 *= 0.125; lk0 *= 0.125; lt1 *= 0.125; lk1 *= 0.125;
            double l0 = 0.7 * lt0 + 0.3 * lk0;
            double l1 = 0.7 * lt1 + 0.3 * lk1;
            out[0] = (float)(0.5 * (l0 + l1));
            out[1] = (float)(0.5 * (lt0 + lt1));
            out[2] = (float)(0.5 * (lk0 + lk1));
        }
        __syncthreads();
        // self-clean scratch for the next graph replay (all dice atomics already landed)
        if (t < NI) { g_pos[t] = 0u; g_neg[t] = 0u; }
        {
            double* s = &g_sums[0][0];
            for (int j = t; j < NI * 18; j += 256) s[j] = 0.0;
        }
        if (t == 0) { g_cdone = 0u; g_ddone = 0u; g_anyhist = 0; }
    }
}

// ---------------- launch ----------------
extern "C" void kernel_launch(void* const* d_in, const int* in_sizes, int n_in,
                              void* d_out, int out_size) {
    const float* outs = (const float*)d_in[0];
    const float* labs = (const float*)d_in[1];
    const float* tmg  = (const float*)d_in[2];
    float* out = (float*)d_out;

    k_count<<<8 * CB, 256>>>(labs, tmg);
    k_rare<<<RNB, 256>>>(outs, labs);              // idle (~1 launch) on fast path
    k_dice<<<NI * DB, 256>>>(outs, labs, tmg, out);
}

// round 14
// speedup vs baseline: 1.6228x; 1.0127x over previous
#include <cuda_runtime.h>
#include <math.h>

// ---------------- problem constants ----------------
#define NI      16          // instances; iid = class*8 + b
#define HW      409600      // 640*640
#define HW4     102400      // HW/4
#define HWP     51200       // HW4/2 (pairs of float4)
#define NCH     12
#define NMAPS   6
#define EPSF    1e-4
#define CB      111         // count blocks per batch image (8*111 = 888 = 148*6)
#define DB      37          // dice blocks per instance (16*37 = 592 = 148 SMs * 4 CTAs: ONE wave)
#define RBPI    18          // rare-kernel blocks per instance
#define RNB     (NI*RBPI)   // 288 (co-resident: 148 SMs * 2)

// ---------------- device scratch (zero-initialized at load; self-cleaned each run) ----------------
__device__ unsigned g_cdone;                  // completion counter for k_count
__device__ unsigned g_ddone;                  // completion counter for k_dice
__device__ unsigned g_bar;                    // grid barrier counter for k_rare
__device__ unsigned g_pos[NI], g_neg[NI];
__device__ int      g_mode[NI];               // 0=select-all 1=fallback 2=hist
__device__ int      g_fallback[NI];
__device__ int      g_anyhist;
__device__ unsigned long long g_k[NI];
__device__ float    g_thr[NI];
__device__ unsigned g_selhi[NI], g_krem[NI];
__device__ unsigned g_histhi[NI][8192];       // rare path only (stays zero on fast path)
__device__ unsigned g_histlo[NI][524288];     // rare path only
__device__ double   g_sums[NI][18];           // [0..2]=text a,b,c ; [3+j]=a_k ; [8+j]=b_k ; [13+j]=c_k

// ---------------- helpers ----------------
__device__ __forceinline__ float fsigmoid(float x) {
    float t;
    asm("tanh.approx.f32 %0, %1;" : "=f"(t) : "f"(0.5f * x));
    return fmaf(0.5f, t, 0.5f);
}
__device__ __forceinline__ unsigned keyOf(float x) {
    unsigned u = __float_as_uint(x);
    return (u & 0x80000000u) ? ~u : (u | 0x80000000u);
}
__device__ __forceinline__ float unkey(unsigned k) {
    unsigned u = (k & 0x80000000u) ? (k ^ 0x80000000u) : ~k;
    return __uint_as_float(u);
}

// ---------------- kernel 1: pos/neg counts (2x unrolled, MLP=6) + decide in last block ----------------
__global__ void __launch_bounds__(256) k_count(const float* __restrict__ labs,
                                               const float* __restrict__ tmg) {
    int b  = blockIdx.x / CB;
    int cb = blockIdx.x % CB;
    const float4* g0 = (const float4*)labs + ((size_t)b * NCH + 5)  * HW4;
    const float4* g1 = (const float4*)labs + ((size_t)b * NCH + 11) * HW4;
    const float4* m4 = (const float4*)tmg  + (size_t)b * HW4;

    unsigned p0 = 0, n0 = 0, p1 = 0, n1 = 0;
    for (int pr = cb * 256 + threadIdx.x; pr < HWP; pr += CB * 256) {
        int idx = pr * 2;
        float4 a0 = g0[idx]; float4 a1 = g0[idx + 1];
        float4 c0 = g1[idx]; float4 c1 = g1[idx + 1];
        float4 m0 = m4[idx]; float4 m1 = m4[idx + 1];
        float av[8] = {a0.x, a0.y, a0.z, a0.w, a1.x, a1.y, a1.z, a1.w};
        float cv[8] = {c0.x, c0.y, c0.z, c0.w, c1.x, c1.y, c1.z, c1.w};
        float mv[8] = {m0.x, m0.y, m0.z, m0.w, m1.x, m1.y, m1.z, m1.w};
        #pragma unroll
        for (int e = 0; e < 8; e++) {
            bool tm = mv[e] > 0.5f;
            if (av[e] > 0.5f) { if (tm) p0++; } else n0++;
            if (cv[e] > 0.5f) { if (tm) p1++; } else n1++;
        }
    }
    #pragma unroll
    for (int o = 16; o; o >>= 1) {
        p0 += __shfl_down_sync(0xffffffffu, p0, o);
        n0 += __shfl_down_sync(0xffffffffu, n0, o);
        p1 += __shfl_down_sync(0xffffffffu, p1, o);
        n1 += __shfl_down_sync(0xffffffffu, n1, o);
    }
    __shared__ unsigned sp0, sn0, sp1, sn1;
    if (threadIdx.x == 0) { sp0 = sn0 = sp1 = sn1 = 0u; }
    __syncthreads();
    if ((threadIdx.x & 31) == 0) {
        atomicAdd(&sp0, p0); atomicAdd(&sn0, n0);
        atomicAdd(&sp1, p1); atomicAdd(&sn1, n1);
    }
    __syncthreads();
    if (threadIdx.x == 0) {
        atomicAdd(&g_pos[b],     sp0); atomicAdd(&g_neg[b],     sn0);
        atomicAdd(&g_pos[8 + b], sp1); atomicAdd(&g_neg[8 + b], sn1);
    }

    // last-finishing block runs decide
    __shared__ unsigned amLast;
    __threadfence();
    if (threadIdx.x == 0)
        amLast = (atomicAdd(&g_cdone, 1u) == (unsigned)gridDim.x - 1u) ? 1u : 0u;
    __syncthreads();
    if (amLast) {
        __shared__ int any;
        if (threadIdx.x == 0) any = 0;
        __syncthreads();
        if (threadIdx.x < NI) {
            int t = threadIdx.x;
            unsigned p = *(volatile unsigned*)&g_pos[t];
            unsigned n = *(volatile unsigned*)&g_neg[t];
            unsigned long long k = (unsigned long long)p * 3ull;
            if (k > n) k = n;
            int mode, fb = 0; float thr = 0.f;
            if (p == 0u || k == 0ull)           { mode = 1; fb = 1; }
            else if (k == (unsigned long long)n){ mode = 0; thr = -INFINITY; }
            else                                 { mode = 2; atomicExch(&any, 1); }
            g_mode[t] = mode; g_fallback[t] = fb; g_thr[t] = thr; g_k[t] = k;
        }
        __syncthreads();
        if (threadIdx.x == 0) { g_anyhist = any; __threadfence(); }
    }
}

// ---------------- kernel 2 (persistent, guarded): exact radix-select threshold ----------------
__device__ __forceinline__ void gridbar(int phase) {
    __syncthreads();
    __threadfence();
    if (threadIdx.x == 0) {
        atomicAdd(&g_bar, 1u);
        unsigned tgt = (unsigned)phase * (unsigned)RNB;
        while (*(volatile unsigned*)&g_bar < tgt) { }
    }
    __syncthreads();
    __threadfence();
}

__global__ void __launch_bounds__(256, 2) k_rare(const float* __restrict__ outs,
                                                 const float* __restrict__ labs) {
    if (*(volatile int*)&g_anyhist == 0) return;     // fast path: all 288 blocks exit

    const int blk = blockIdx.x;
    const int inst_lin = blk / RBPI;
    const int slice = blk % RBPI;
    const int b = inst_lin >> 1, i = inst_lin & 1;
    const int iid = i * 8 + b;
    const int tid = threadIdx.x;
    const int mymode = *(volatile int*)&g_mode[iid];

    const int ch = i * NMAPS + (NMAPS - 1);
    const float4* sc4 = (const float4*)outs + ((size_t)b * NCH + ch) * HW4;
    const float4* gt4 = (const float4*)labs + ((size_t)b * NCH + ch) * HW4;

    __shared__ unsigned shist[8192];
    __shared__ unsigned long long csum[256];

    // phase 1: top-13-bit histogram of negative keys
    if (mymode == 2) {
        for (int j = tid; j < 8192; j += 256) shist[j] = 0u;
        __syncthreads();
        for (int idx = slice * 256 + tid; idx < HW4; idx += RBPI * 256) {
            float4 s = sc4[idx]; float4 g = gt4[idx];
            float sv[4] = {s.x, s.y, s.z, s.w};
            float gg[4] = {g.x, g.y, g.z, g.w};
            #pragma unroll
            for (int e = 0; e < 4; e++)
                if (gg[e] <= 0.5f) atomicAdd(&shist[keyOf(sv[e]) >> 19], 1u);
        }
        __syncthreads();
        for (int j = tid; j < 8192; j += 256) {
            unsigned c = shist[j];
            if (c) atomicAdd(&g_histhi[iid][j], c);
        }
    }
    gridbar(1);

    // phase 2: scan hi descending (block t handles instance t)
    if (blk < NI && *(volatile int*)&g_mode[blk] == 2) {
        unsigned long long s = 0;
        int hi = 8192 - tid * 32;
        for (int bn = hi - 1; bn >= hi - 32; bn--) s += g_histhi[blk][bn];
        csum[tid] = s;
        __syncthreads();
        if (tid == 0) {
            unsigned long long k = g_k[blk], cum = 0;
            for (int c = 0; c < 256; c++) {
                if (cum + csum[c] >= k) {
                    int h2 = 8192 - c * 32;
                    for (int bn = h2 - 1; bn >= h2 - 32; bn--) {
                        unsigned long long hv = g_histhi[blk][bn];
                        if (cum + hv >= k) { g_selhi[blk] = (unsigned)bn; g_krem[blk] = (unsigned)(k - cum); goto donehi; }
                        cum += hv;
                    }
                }
                cum += csum[c];
            }
            donehi: ;
        }
    }
    gridbar(2);

    // phase 3: low-19-bit histogram among matching hi-bin
    if (mymode == 2) {
        unsigned sel = *(volatile unsigned*)&g_selhi[iid];
        for (int idx = slice * 256 + tid; idx < HW4; idx += RBPI * 256) {
            float4 s = sc4[idx]; float4 g = gt4[idx];
            float sv[4] = {s.x, s.y, s.z, s.w};
            float gg[4] = {g.x, g.y, g.z, g.w};
            #pragma unroll
            for (int e = 0; e < 4; e++) {
                if (gg[e] <= 0.5f) {
                    unsigned kk = keyOf(sv[e]);
                    if ((kk >> 19) == sel) atomicAdd(&g_histlo[iid][kk & 0x7FFFFu], 1u);
                }
            }
        }
    }
    gridbar(3);

    // phase 4: scan lo -> exact threshold; then clear dirtied histograms
    if (blk < NI && *(volatile int*)&g_mode[blk] == 2) {
        unsigned long long s = 0;
        int hi = 524288 - tid * 2048;
        for (int bn = hi - 1; bn >= hi - 2048; bn--) s += g_histlo[blk][bn];
        csum[tid] = s;
        __syncthreads();
        if (tid == 0) {
            unsigned long long k = (unsigned long long)g_krem[blk], cum = 0;
            unsigned sel = g_selhi[blk];
            for (int c = 0; c < 256; c++) {
                if (cum + csum[c] >= k) {
                    int h2 = 524288 - c * 2048;
                    for (int bn = h2 - 1; bn >= h2 - 2048; bn--) {
                        unsigned long long hv = g_histlo[blk][bn];
                        if (cum + hv >= k) { g_thr[blk] = unkey((sel << 19) | (unsigned)bn); goto donelo; }
                        cum += hv;
                    }
                }
                cum += csum[c];
            }
            donelo: ;
        }
    }
    __syncthreads();
    {   // clear histograms so next run starts zeroed
        unsigned* hi2 = &g_histhi[0][0];
        unsigned* lo2 = &g_histlo[0][0];
        int gt0 = blk * 256 + tid, gs = RNB * 256;
        for (int j = gt0; j < NI * 8192; j += gs) hi2[j] = 0u;
        for (size_t j = gt0; j < (size_t)NI * 524288; j += gs) lo2[j] = 0u;
    }
    gridbar(4);
    if (blk == 0 && tid == 0) g_bar = 0u;   // reset barrier counter for next run
}

// ---------------- kernel 3: fused dice + finalize + scratch cleanup ----------------
__global__ void __launch_bounds__(256) k_dice(const float* __restrict__ outs,
                                              const float* __restrict__ labs,
                                              const float* __restrict__ tmg,
                                              float* __restrict__ out) {
    int inst = blockIdx.x / DB;
    int cb   = blockIdx.x % DB;
    int b = inst >> 1, i = inst & 1;
    int iid = i * 8 + b;
    const float thr = g_thr[iid];
    const int   fb  = g_fallback[iid];

    const float4* ob = (const float4*)outs + ((size_t)b * NCH + i * NMAPS) * HW4;
    const float4* lb = (const float4*)labs + ((size_t)b * NCH + i * NMAPS) * HW4;
    const float4* m4 = (const float4*)tmg  + (size_t)b * HW4;

    float acc[18];
    #pragma unroll
    for (int j = 0; j < 18; j++) acc[j] = 0.f;

    for (int idx = cb * 256 + threadIdx.x; idx < HW4; idx += DB * 256) {
        float4 t = ob[5 * HW4 + idx];
        float4 g = lb[5 * HW4 + idx];
        float4 m = m4[idx];
        float tv[4] = {t.x, t.y, t.z, t.w};
        float gv[4] = {g.x, g.y, g.z, g.w};
        float mv[4] = {m.x, m.y, m.z, m.w};
        float selk[4];
        #pragma unroll
        for (int e = 0; e < 4; e++) {
            float sc = tv[e], gval = gv[e], mval = mv[e];
            float st = fb ? mval
                          : (((sc >= thr) || (gval > 0.5f)) && (mval > 0.5f) ? 1.f : 0.f);
            float sg = fsigmoid(sc);
            float p = sg * st, tt = gval * st;
            acc[0] = fmaf(p, tt, acc[0]);
            acc[1] = fmaf(p, p,  acc[1]);
            acc[2] = fmaf(tt, tt, acc[2]);
            selk[e] = (sc > 0.f && mval > 0.5f) ? 1.f : 0.f;
        }
        #pragma unroll
        for (int j = 0; j < 5; j++) {
            float4 kv = ob[(size_t)j * HW4 + idx];
            float4 gk = lb[(size_t)j * HW4 + idx];
            float kvv[4] = {kv.x, kv.y, kv.z, kv.w};
            float gkk[4] = {gk.x, gk.y, gk.z, gk.w};
            #pragma unroll
            for (int e = 0; e < 4; e++) {
                float sg = fsigmoid(kvv[e]);
                float p = sg * selk[e], tt = gkk[e] * selk[e];
                acc[3 + j]  = fmaf(p, tt, acc[3 + j]);
                acc[8 + j]  = fmaf(p, p,  acc[8 + j]);
                acc[13 + j] = fmaf(tt, tt, acc[13 + j]);
            }
        }
    }

    #pragma unroll
    for (int j = 0; j < 18; j++) {
        float v = acc[j];
        #pragma unroll
        for (int o = 16; o; o >>= 1) v += __shfl_down_sync(0xffffffffu, v, o);
        acc[j] = v;
    }
    __shared__ float bsum[18];
    if (threadIdx.x < 18) bsum[threadIdx.x] = 0.f;
    __syncthreads();
    if ((threadIdx.x & 31) == 0) {
        #pragma unroll
        for (int j = 0; j < 18; j++) atomicAdd(&bsum[j], acc[j]);
    }
    __syncthreads();
    if (threadIdx.x < 18) atomicAdd(&g_sums[iid][threadIdx.x], (double)bsum[threadIdx.x]);

    // ---- last-finishing block: finalize 3 outputs, then self-clean ALL scratch ----
    __shared__ unsigned amLast;
    __threadfence();
    if (threadIdx.x == 0)
        amLast = (atomicAdd(&g_ddone, 1u) == (unsigned)gridDim.x - 1u) ? 1u : 0u;
    __syncthreads();
    if (amLast) {
        __shared__ double slt[NI], slk[NI];
        int t = threadIdx.x;
        if (t < NI) {
            double a  = *(volatile double*)&g_sums[t][0];
            double bb = *(volatile double*)&g_sums[t][1] + EPSF;
            double cc = *(volatile double*)&g_sums[t][2] + EPSF;
            double lt = 1.0 - 2.0 * a / (bb + cc);
            double lk = 0.0;
            for (int j = 0; j < 5; j++) {
                double aj = *(volatile double*)&g_sums[t][3 + j];
                double bj = *(volatile double*)&g_sums[t][8 + j] + EPSF;
                double cj = *(volatile double*)&g_sums[t][13 + j] + EPSF;
                lk += 1.0 - 2.0 * aj / (bj + cj);
            }
            lk *= 0.2;
            slt[t] = lt; slk[t] = lk;
        }
        __syncthreads();
        if (t == 0) {
            double lt0 = 0, lt1 = 0, lk0 = 0, lk1 = 0;
            for (int b2 = 0; b2 < 8; b2++) {
                lt0 += slt[b2];     lk0 += slk[b2];
                lt1 += slt[8 + b2]; lk1 += slk[8 + b2];
            }
            lt0 *= 0.125; lk0 *= 0.125; lt1 *= 0.125; lk1 *= 0.125;
            double l0 = 0.7 * lt0 + 0.3 * lk0;
            double l1 = 0.7 * lt1 + 0.3 * lk1;
            out[0] = (float)(0.5 * (l0 + l1));
            out[1] = (float)(0.5 * (lt0 + lt1));
            out[2] = (float)(0.5 * (lk0 + lk1));
        }
        __syncthreads();
        // self-clean scratch for the next graph replay (all dice atomics already landed)
        if (t < NI) { g_pos[t] = 0u; g_neg[t] = 0u; }
        {
            double* s = &g_sums[0][0];
            for (int j = t; j < NI * 18; j += 256) s[j] = 0.0;
        }
        if (t == 0) { g_cdone = 0u; g_ddone = 0u; g_anyhist = 0; }
    }
}

// ---------------- launch ----------------
extern "C" void kernel_launch(void* const* d_in, const int* in_sizes, int n_in,
                              void* d_out, int out_size) {
    const float* outs = (const float*)d_in[0];
    const float* labs = (const float*)d_in[1];
    const float* tmg  = (const float*)d_in[2];
    float* out = (float*)d_out;

    k_count<<<8 * CB, 256>>>(labs, tmg);
    k_rare<<<RNB, 256>>>(outs, labs);              // idle (~1 launch) on fast path
    k_dice<<<NI * DB, 256>>>(outs, labs, tmg, out);
}